// round 2
// baseline (speedup 1.0000x reference)
#include <cuda_runtime.h>
#include <math.h>

// Problem constants
#define BATCH 4
#define SEQ   2048
#define DQ    1024
#define DKV   768
#define NH    4
#define HD    256

// GEMM tiling
#define BM 128
#define BN 128
#define BK 16
#define PAD 4

// -------- scratch (device globals: sanctioned workaround, no cudaMalloc) ----
__device__ float g_qp[(long long)BATCH * SEQ * DQ];     // 32 MB
__device__ float g_kp[(long long)BATCH * SEQ * DQ];     // 32 MB
__device__ float g_vp[(long long)BATCH * SEQ * DQ];     // 32 MB
__device__ float g_ctx[(long long)BATCH * SEQ * DQ];    // 32 MB
__device__ float g_scores[(long long)BATCH * NH * SEQ * SEQ]; // 256 MB

// ---------------------------------------------------------------------------
// C[m,n] = alpha * sum_k A[m,k] * B[n,k]  (+ bias[n])     "NT" GEMM
// batched: z -> (bz = z/nh, hz = z%nh); per-operand (batch, head) strides.
// Requires M%128==0, N%128==0, K%16==0, all leading dims %4==0.
// ---------------------------------------------------------------------------
__global__ __launch_bounds__(256, 2)
void gemm_nt_kernel(const float* __restrict__ A, const float* __restrict__ B,
                    const float* __restrict__ bias, float* __restrict__ C,
                    int K, int lda, int ldb, int ldc, int nh,
                    long long sAb, long long sAh,
                    long long sBb, long long sBh,
                    long long sCb, long long sCh,
                    float alpha)
{
    const int z = blockIdx.z;
    const int bz = z / nh, hz = z % nh;
    A += bz * sAb + hz * sAh;
    B += bz * sBb + hz * sBh;
    C += bz * sCb + hz * sCh;

    __shared__ float As[2][BK][BM + PAD];
    __shared__ float Bs[2][BK][BN + PAD];

    const int tid = threadIdx.x;
    const int tx = tid & 15, ty = tid >> 4;
    const int row0 = ty * 8, col0 = tx * 8;
    const int bm = blockIdx.y * BM, bn = blockIdx.x * BN;

    float acc[8][8];
    #pragma unroll
    for (int i = 0; i < 8; ++i)
        #pragma unroll
        for (int j = 0; j < 8; ++j)
            acc[i][j] = 0.0f;

    const int KT = K / BK;

    float4 pa[2], pb[2];
    // prologue: tile 0 -> buffer 0
    #pragma unroll
    for (int i = 0; i < 2; ++i) {
        int idx = tid + i * 256;
        int r = idx >> 2, kq = idx & 3;
        pa[i] = *(const float4*)(A + (long long)(bm + r) * lda + kq * 4);
        pb[i] = *(const float4*)(B + (long long)(bn + r) * ldb + kq * 4);
    }
    #pragma unroll
    for (int i = 0; i < 2; ++i) {
        int idx = tid + i * 256;
        int r = idx >> 2, kq = idx & 3;
        As[0][kq * 4 + 0][r] = pa[i].x;
        As[0][kq * 4 + 1][r] = pa[i].y;
        As[0][kq * 4 + 2][r] = pa[i].z;
        As[0][kq * 4 + 3][r] = pa[i].w;
        Bs[0][kq * 4 + 0][r] = pb[i].x;
        Bs[0][kq * 4 + 1][r] = pb[i].y;
        Bs[0][kq * 4 + 2][r] = pb[i].z;
        Bs[0][kq * 4 + 3][r] = pb[i].w;
    }
    __syncthreads();

    for (int kt = 0; kt < KT; ++kt) {
        const int cur = kt & 1, nxt = cur ^ 1;
        const bool more = (kt + 1 < KT);
        if (more) {
            const int k0 = (kt + 1) * BK;
            #pragma unroll
            for (int i = 0; i < 2; ++i) {
                int idx = tid + i * 256;
                int r = idx >> 2, kq = idx & 3;
                pa[i] = *(const float4*)(A + (long long)(bm + r) * lda + k0 + kq * 4);
                pb[i] = *(const float4*)(B + (long long)(bn + r) * ldb + k0 + kq * 4);
            }
        }
        #pragma unroll
        for (int k = 0; k < BK; ++k) {
            float a[8], b[8];
            *(float4*)(&a[0]) = *(const float4*)(&As[cur][k][row0]);
            *(float4*)(&a[4]) = *(const float4*)(&As[cur][k][row0 + 4]);
            *(float4*)(&b[0]) = *(const float4*)(&Bs[cur][k][col0]);
            *(float4*)(&b[4]) = *(const float4*)(&Bs[cur][k][col0 + 4]);
            #pragma unroll
            for (int i = 0; i < 8; ++i)
                #pragma unroll
                for (int j = 0; j < 8; ++j)
                    acc[i][j] = fmaf(a[i], b[j], acc[i][j]);
        }
        if (more) {
            #pragma unroll
            for (int i = 0; i < 2; ++i) {
                int idx = tid + i * 256;
                int r = idx >> 2, kq = idx & 3;
                As[nxt][kq * 4 + 0][r] = pa[i].x;
                As[nxt][kq * 4 + 1][r] = pa[i].y;
                As[nxt][kq * 4 + 2][r] = pa[i].z;
                As[nxt][kq * 4 + 3][r] = pa[i].w;
                Bs[nxt][kq * 4 + 0][r] = pb[i].x;
                Bs[nxt][kq * 4 + 1][r] = pb[i].y;
                Bs[nxt][kq * 4 + 2][r] = pb[i].z;
                Bs[nxt][kq * 4 + 3][r] = pb[i].w;
            }
        }
        __syncthreads();
    }

    float bv[8];
    #pragma unroll
    for (int j = 0; j < 8; ++j)
        bv[j] = bias ? bias[bn + col0 + j] : 0.0f;

    #pragma unroll
    for (int i = 0; i < 8; ++i) {
        #pragma unroll
        for (int j = 0; j < 8; j += 4) {
            float4 v;
            v.x = acc[i][j + 0] * alpha + bv[j + 0];
            v.y = acc[i][j + 1] * alpha + bv[j + 1];
            v.z = acc[i][j + 2] * alpha + bv[j + 2];
            v.w = acc[i][j + 3] * alpha + bv[j + 3];
            *(float4*)(C + (long long)(bm + row0 + i) * ldc + bn + col0 + j) = v;
        }
    }
}

// ---------------------------------------------------------------------------
// C[m,n] = sum_k A[m,k] * B[k,n]            "NN" GEMM (B is [K,N] row-major)
// ---------------------------------------------------------------------------
__global__ __launch_bounds__(256, 2)
void gemm_nn_kernel(const float* __restrict__ A, const float* __restrict__ B,
                    float* __restrict__ C,
                    int K, int lda, int ldb, int ldc, int nh,
                    long long sAb, long long sAh,
                    long long sBb, long long sBh,
                    long long sCb, long long sCh)
{
    const int z = blockIdx.z;
    const int bz = z / nh, hz = z % nh;
    A += bz * sAb + hz * sAh;
    B += bz * sBb + hz * sBh;
    C += bz * sCb + hz * sCh;

    __shared__ float As[2][BK][BM + PAD];
    __shared__ float Bs[2][BK][BN + PAD];

    const int tid = threadIdx.x;
    const int tx = tid & 15, ty = tid >> 4;
    const int row0 = ty * 8, col0 = tx * 8;
    const int bm = blockIdx.y * BM, bn = blockIdx.x * BN;

    float acc[8][8];
    #pragma unroll
    for (int i = 0; i < 8; ++i)
        #pragma unroll
        for (int j = 0; j < 8; ++j)
            acc[i][j] = 0.0f;

    const int KT = K / BK;

    float4 pa[2], pb[2];
    #pragma unroll
    for (int i = 0; i < 2; ++i) {
        int idx = tid + i * 256;
        int r = idx >> 2, kq = idx & 3;            // A: row r, k-quad kq
        int kr = idx >> 5, nq = idx & 31;          // B: k-row kr, n-quad nq
        pa[i] = *(const float4*)(A + (long long)(bm + r) * lda + kq * 4);
        pb[i] = *(const float4*)(B + (long long)kr * ldb + bn + nq * 4);
    }
    #pragma unroll
    for (int i = 0; i < 2; ++i) {
        int idx = tid + i * 256;
        int r = idx >> 2, kq = idx & 3;
        int kr = idx >> 5, nq = idx & 31;
        As[0][kq * 4 + 0][r] = pa[i].x;
        As[0][kq * 4 + 1][r] = pa[i].y;
        As[0][kq * 4 + 2][r] = pa[i].z;
        As[0][kq * 4 + 3][r] = pa[i].w;
        *(float4*)(&Bs[0][kr][nq * 4]) = pb[i];
    }
    __syncthreads();

    for (int kt = 0; kt < KT; ++kt) {
        const int cur = kt & 1, nxt = cur ^ 1;
        const bool more = (kt + 1 < KT);
        if (more) {
            const int k0 = (kt + 1) * BK;
            #pragma unroll
            for (int i = 0; i < 2; ++i) {
                int idx = tid + i * 256;
                int r = idx >> 2, kq = idx & 3;
                int kr = idx >> 5, nq = idx & 31;
                pa[i] = *(const float4*)(A + (long long)(bm + r) * lda + k0 + kq * 4);
                pb[i] = *(const float4*)(B + (long long)(k0 + kr) * ldb + bn + nq * 4);
            }
        }
        #pragma unroll
        for (int k = 0; k < BK; ++k) {
            float a[8], b[8];
            *(float4*)(&a[0]) = *(const float4*)(&As[cur][k][row0]);
            *(float4*)(&a[4]) = *(const float4*)(&As[cur][k][row0 + 4]);
            *(float4*)(&b[0]) = *(const float4*)(&Bs[cur][k][col0]);
            *(float4*)(&b[4]) = *(const float4*)(&Bs[cur][k][col0 + 4]);
            #pragma unroll
            for (int i = 0; i < 8; ++i)
                #pragma unroll
                for (int j = 0; j < 8; ++j)
                    acc[i][j] = fmaf(a[i], b[j], acc[i][j]);
        }
        if (more) {
            #pragma unroll
            for (int i = 0; i < 2; ++i) {
                int idx = tid + i * 256;
                int r = idx >> 2, kq = idx & 3;
                int kr = idx >> 5, nq = idx & 31;
                As[nxt][kq * 4 + 0][r] = pa[i].x;
                As[nxt][kq * 4 + 1][r] = pa[i].y;
                As[nxt][kq * 4 + 2][r] = pa[i].z;
                As[nxt][kq * 4 + 3][r] = pa[i].w;
                *(float4*)(&Bs[nxt][kr][nq * 4]) = pb[i];
            }
        }
        __syncthreads();
    }

    #pragma unroll
    for (int i = 0; i < 8; ++i) {
        #pragma unroll
        for (int j = 0; j < 8; j += 4) {
            float4 v;
            v.x = acc[i][j + 0];
            v.y = acc[i][j + 1];
            v.z = acc[i][j + 2];
            v.w = acc[i][j + 3];
            *(float4*)(C + (long long)(bm + row0 + i) * ldc + bn + col0 + j) = v;
        }
    }
}

// ---------------------------------------------------------------------------
// Row softmax, ncols = 2048, 256 threads, 8 elems/thread
// ---------------------------------------------------------------------------
__device__ __forceinline__ float warp_max(float v) {
    #pragma unroll
    for (int o = 16; o > 0; o >>= 1) v = fmaxf(v, __shfl_xor_sync(0xffffffffu, v, o));
    return v;
}
__device__ __forceinline__ float warp_sum(float v) {
    #pragma unroll
    for (int o = 16; o > 0; o >>= 1) v += __shfl_xor_sync(0xffffffffu, v, o);
    return v;
}

__global__ __launch_bounds__(256)
void softmax_kernel(float* __restrict__ S, int ncols)
{
    float* p = S + (long long)blockIdx.x * ncols;
    const int tid = threadIdx.x;
    const int wid = tid >> 5, lid = tid & 31;
    __shared__ float red[8];

    float v[8];
    float m = -1e30f;
    #pragma unroll
    for (int i = 0; i < 8; ++i) {
        v[i] = p[tid + i * 256];
        m = fmaxf(m, v[i]);
    }
    m = warp_max(m);
    if (lid == 0) red[wid] = m;
    __syncthreads();
    if (wid == 0) {
        float t = (lid < 8) ? red[lid] : -1e30f;   // FIX: each partial once
        t = warp_max(t);
        if (lid == 0) red[0] = t;
    }
    __syncthreads();
    m = red[0];
    __syncthreads();

    float s = 0.0f;
    #pragma unroll
    for (int i = 0; i < 8; ++i) {
        v[i] = expf(v[i] - m);
        s += v[i];
    }
    s = warp_sum(s);
    if (lid == 0) red[wid] = s;
    __syncthreads();
    if (wid == 0) {
        float t = (lid < 8) ? red[lid] : 0.0f;     // FIX: was red[lid&7] => 4x oversum
        t = warp_sum(t);
        if (lid == 0) red[0] = t;
    }
    __syncthreads();
    const float inv = 1.0f / red[0];

    #pragma unroll
    for (int i = 0; i < 8; ++i)
        p[tid + i * 256] = v[i] * inv;
}

// ---------------------------------------------------------------------------
extern "C" void kernel_launch(void* const* d_in, const int* in_sizes, int n_in,
                              void* d_out, int out_size)
{
    const float* q  = (const float*)d_in[0];
    const float* kv = (const float*)d_in[1];
    const float* Wq = (const float*)d_in[2];
    const float* Wk = (const float*)d_in[3];
    const float* Wv = (const float*)d_in[4];
    const float* Wo = (const float*)d_in[5];
    const float* bo = (const float*)d_in[6];
    float* out = (float*)d_out;

    float *qp, *kp, *vp, *ctx, *sc;
    cudaGetSymbolAddress((void**)&qp,  g_qp);
    cudaGetSymbolAddress((void**)&kp,  g_kp);
    cudaGetSymbolAddress((void**)&vp,  g_vp);
    cudaGetSymbolAddress((void**)&ctx, g_ctx);
    cudaGetSymbolAddress((void**)&sc,  g_scores);

    const dim3 blk(256);
    const int MT = BATCH * SEQ;              // 8192 flattened rows
    const float scale = 1.0f / 16.0f;        // HD^-0.5 = 256^-0.5

    // 1) qp = q @ Wq^T            [8192,1024] x [1024,1024]^T
    gemm_nt_kernel<<<dim3(DQ / BN, MT / BM, 1), blk>>>(
        q, Wq, nullptr, qp, DQ, DQ, DQ, DQ, 1,
        0, 0, 0, 0, 0, 0, 1.0f);

    // 2) kp = kv @ Wk^T           [8192,768] x [1024,768]^T
    gemm_nt_kernel<<<dim3(DQ / BN, MT / BM, 1), blk>>>(
        kv, Wk, nullptr, kp, DKV, DKV, DKV, DQ, 1,
        0, 0, 0, 0, 0, 0, 1.0f);

    // 3) vp = kv @ Wv^T
    gemm_nt_kernel<<<dim3(DQ / BN, MT / BM, 1), blk>>>(
        kv, Wv, nullptr, vp, DKV, DKV, DKV, DQ, 1,
        0, 0, 0, 0, 0, 0, 1.0f);

    // 4) scores[b,h] = scale * qh @ kh^T    per (b,h): [2048,256] x [2048,256]^T
    gemm_nt_kernel<<<dim3(SEQ / BN, SEQ / BM, BATCH * NH), blk>>>(
        qp, kp, nullptr, sc, HD, DQ, DQ, SEQ, NH,
        (long long)SEQ * DQ, HD,
        (long long)SEQ * DQ, HD,
        (long long)NH * SEQ * SEQ, (long long)SEQ * SEQ,
        scale);

    // 5) softmax over rows of scores
    softmax_kernel<<<dim3(BATCH * NH * SEQ), blk>>>(sc, SEQ);

    // 6) ctx[b,h] = P @ vh        per (b,h): [2048,2048] x [2048,256]
    gemm_nn_kernel<<<dim3(HD / BN, SEQ / BM, BATCH * NH), blk>>>(
        sc, vp, ctx, SEQ, SEQ, DQ, DQ, NH,
        (long long)NH * SEQ * SEQ, (long long)SEQ * SEQ,
        (long long)SEQ * DQ, HD,
        (long long)SEQ * DQ, HD);

    // 7) out = ctx @ Wo^T + bo    [8192,1024] x [1024,1024]^T
    gemm_nt_kernel<<<dim3(DQ / BN, MT / BM, 1), blk>>>(
        ctx, Wo, bo, out, DQ, DQ, DQ, DQ, 1,
        0, 0, 0, 0, 0, 0, 1.0f);
}

// round 3
// speedup vs baseline: 1.0002x; 1.0002x over previous
#include <cuda_runtime.h>
#include <math.h>

// Problem constants
#define BATCH 4
#define SEQ   2048
#define DQ    1024
#define DKV   768
#define NH    4
#define HD    256

// GEMM tiling
#define BM 128
#define BN 128
#define BK 16
#define PAD 4

// -------- scratch (device globals: sanctioned workaround, no cudaMalloc) ----
__device__ float g_qp[(long long)BATCH * SEQ * DQ];     // 32 MB
__device__ float g_kp[(long long)BATCH * SEQ * DQ];     // 32 MB
__device__ float g_vp[(long long)BATCH * SEQ * DQ];     // 32 MB
__device__ float g_ctx[(long long)BATCH * SEQ * DQ];    // 32 MB
__device__ float g_scores[(long long)BATCH * NH * SEQ * SEQ]; // 256 MB

// ---------------------------------------------------------------------------
// C[m,n] = alpha * sum_k A[m,k] * B[n,k]  (+ bias[n])     "NT" GEMM
// batched: z -> (bz = z/nh, hz = z%nh); per-operand (batch, head) strides.
// Requires M%128==0, N%128==0, K%16==0, all leading dims %4==0.
// ---------------------------------------------------------------------------
__global__ __launch_bounds__(256, 2)
void gemm_nt_kernel(const float* __restrict__ A, const float* __restrict__ B,
                    const float* __restrict__ bias, float* __restrict__ C,
                    int K, int lda, int ldb, int ldc, int nh,
                    long long sAb, long long sAh,
                    long long sBb, long long sBh,
                    long long sCb, long long sCh,
                    float alpha)
{
    const int z = blockIdx.z;
    const int bz = z / nh, hz = z % nh;
    A += bz * sAb + hz * sAh;
    B += bz * sBb + hz * sBh;
    C += bz * sCb + hz * sCh;

    __shared__ float As[2][BK][BM + PAD];
    __shared__ float Bs[2][BK][BN + PAD];

    const int tid = threadIdx.x;
    const int tx = tid & 15, ty = tid >> 4;
    const int row0 = ty * 8, col0 = tx * 8;
    const int bm = blockIdx.y * BM, bn = blockIdx.x * BN;

    float acc[8][8];
    #pragma unroll
    for (int i = 0; i < 8; ++i)
        #pragma unroll
        for (int j = 0; j < 8; ++j)
            acc[i][j] = 0.0f;

    const int KT = K / BK;

    float4 pa[2], pb[2];
    // prologue: tile 0 -> buffer 0
    #pragma unroll
    for (int i = 0; i < 2; ++i) {
        int idx = tid + i * 256;
        int r = idx >> 2, kq = idx & 3;
        pa[i] = *(const float4*)(A + (long long)(bm + r) * lda + kq * 4);
        pb[i] = *(const float4*)(B + (long long)(bn + r) * ldb + kq * 4);
    }
    #pragma unroll
    for (int i = 0; i < 2; ++i) {
        int idx = tid + i * 256;
        int r = idx >> 2, kq = idx & 3;
        As[0][kq * 4 + 0][r] = pa[i].x;
        As[0][kq * 4 + 1][r] = pa[i].y;
        As[0][kq * 4 + 2][r] = pa[i].z;
        As[0][kq * 4 + 3][r] = pa[i].w;
        Bs[0][kq * 4 + 0][r] = pb[i].x;
        Bs[0][kq * 4 + 1][r] = pb[i].y;
        Bs[0][kq * 4 + 2][r] = pb[i].z;
        Bs[0][kq * 4 + 3][r] = pb[i].w;
    }
    __syncthreads();

    for (int kt = 0; kt < KT; ++kt) {
        const int cur = kt & 1, nxt = cur ^ 1;
        const bool more = (kt + 1 < KT);
        if (more) {
            const int k0 = (kt + 1) * BK;
            #pragma unroll
            for (int i = 0; i < 2; ++i) {
                int idx = tid + i * 256;
                int r = idx >> 2, kq = idx & 3;
                pa[i] = *(const float4*)(A + (long long)(bm + r) * lda + k0 + kq * 4);
                pb[i] = *(const float4*)(B + (long long)(bn + r) * ldb + k0 + kq * 4);
            }
        }
        #pragma unroll
        for (int k = 0; k < BK; ++k) {
            float a[8], b[8];
            *(float4*)(&a[0]) = *(const float4*)(&As[cur][k][row0]);
            *(float4*)(&a[4]) = *(const float4*)(&As[cur][k][row0 + 4]);
            *(float4*)(&b[0]) = *(const float4*)(&Bs[cur][k][col0]);
            *(float4*)(&b[4]) = *(const float4*)(&Bs[cur][k][col0 + 4]);
            #pragma unroll
            for (int i = 0; i < 8; ++i)
                #pragma unroll
                for (int j = 0; j < 8; ++j)
                    acc[i][j] = fmaf(a[i], b[j], acc[i][j]);
        }
        if (more) {
            #pragma unroll
            for (int i = 0; i < 2; ++i) {
                int idx = tid + i * 256;
                int r = idx >> 2, kq = idx & 3;
                As[nxt][kq * 4 + 0][r] = pa[i].x;
                As[nxt][kq * 4 + 1][r] = pa[i].y;
                As[nxt][kq * 4 + 2][r] = pa[i].z;
                As[nxt][kq * 4 + 3][r] = pa[i].w;
                Bs[nxt][kq * 4 + 0][r] = pb[i].x;
                Bs[nxt][kq * 4 + 1][r] = pb[i].y;
                Bs[nxt][kq * 4 + 2][r] = pb[i].z;
                Bs[nxt][kq * 4 + 3][r] = pb[i].w;
            }
        }
        __syncthreads();
    }

    float bv[8];
    #pragma unroll
    for (int j = 0; j < 8; ++j)
        bv[j] = bias ? bias[bn + col0 + j] : 0.0f;

    #pragma unroll
    for (int i = 0; i < 8; ++i) {
        #pragma unroll
        for (int j = 0; j < 8; j += 4) {
            float4 v;
            v.x = acc[i][j + 0] * alpha + bv[j + 0];
            v.y = acc[i][j + 1] * alpha + bv[j + 1];
            v.z = acc[i][j + 2] * alpha + bv[j + 2];
            v.w = acc[i][j + 3] * alpha + bv[j + 3];
            *(float4*)(C + (long long)(bm + row0 + i) * ldc + bn + col0 + j) = v;
        }
    }
}

// ---------------------------------------------------------------------------
// C[m,n] = sum_k A[m,k] * B[k,n]            "NN" GEMM (B is [K,N] row-major)
// ---------------------------------------------------------------------------
__global__ __launch_bounds__(256, 2)
void gemm_nn_kernel(const float* __restrict__ A, const float* __restrict__ B,
                    float* __restrict__ C,
                    int K, int lda, int ldb, int ldc, int nh,
                    long long sAb, long long sAh,
                    long long sBb, long long sBh,
                    long long sCb, long long sCh)
{
    const int z = blockIdx.z;
    const int bz = z / nh, hz = z % nh;
    A += bz * sAb + hz * sAh;
    B += bz * sBb + hz * sBh;
    C += bz * sCb + hz * sCh;

    __shared__ float As[2][BK][BM + PAD];
    __shared__ float Bs[2][BK][BN + PAD];

    const int tid = threadIdx.x;
    const int tx = tid & 15, ty = tid >> 4;
    const int row0 = ty * 8, col0 = tx * 8;
    const int bm = blockIdx.y * BM, bn = blockIdx.x * BN;

    float acc[8][8];
    #pragma unroll
    for (int i = 0; i < 8; ++i)
        #pragma unroll
        for (int j = 0; j < 8; ++j)
            acc[i][j] = 0.0f;

    const int KT = K / BK;

    float4 pa[2], pb[2];
    #pragma unroll
    for (int i = 0; i < 2; ++i) {
        int idx = tid + i * 256;
        int r = idx >> 2, kq = idx & 3;            // A: row r, k-quad kq
        int kr = idx >> 5, nq = idx & 31;          // B: k-row kr, n-quad nq
        pa[i] = *(const float4*)(A + (long long)(bm + r) * lda + kq * 4);
        pb[i] = *(const float4*)(B + (long long)kr * ldb + bn + nq * 4);
    }
    #pragma unroll
    for (int i = 0; i < 2; ++i) {
        int idx = tid + i * 256;
        int r = idx >> 2, kq = idx & 3;
        int kr = idx >> 5, nq = idx & 31;
        As[0][kq * 4 + 0][r] = pa[i].x;
        As[0][kq * 4 + 1][r] = pa[i].y;
        As[0][kq * 4 + 2][r] = pa[i].z;
        As[0][kq * 4 + 3][r] = pa[i].w;
        *(float4*)(&Bs[0][kr][nq * 4]) = pb[i];
    }
    __syncthreads();

    for (int kt = 0; kt < KT; ++kt) {
        const int cur = kt & 1, nxt = cur ^ 1;
        const bool more = (kt + 1 < KT);
        if (more) {
            const int k0 = (kt + 1) * BK;
            #pragma unroll
            for (int i = 0; i < 2; ++i) {
                int idx = tid + i * 256;
                int r = idx >> 2, kq = idx & 3;
                int kr = idx >> 5, nq = idx & 31;
                pa[i] = *(const float4*)(A + (long long)(bm + r) * lda + k0 + kq * 4);
                pb[i] = *(const float4*)(B + (long long)(k0 + kr) * ldb + bn + nq * 4);
            }
        }
        #pragma unroll
        for (int k = 0; k < BK; ++k) {
            float a[8], b[8];
            *(float4*)(&a[0]) = *(const float4*)(&As[cur][k][row0]);
            *(float4*)(&a[4]) = *(const float4*)(&As[cur][k][row0 + 4]);
            *(float4*)(&b[0]) = *(const float4*)(&Bs[cur][k][col0]);
            *(float4*)(&b[4]) = *(const float4*)(&Bs[cur][k][col0 + 4]);
            #pragma unroll
            for (int i = 0; i < 8; ++i)
                #pragma unroll
                for (int j = 0; j < 8; ++j)
                    acc[i][j] = fmaf(a[i], b[j], acc[i][j]);
        }
        if (more) {
            #pragma unroll
            for (int i = 0; i < 2; ++i) {
                int idx = tid + i * 256;
                int r = idx >> 2, kq = idx & 3;
                int kr = idx >> 5, nq = idx & 31;
                As[nxt][kq * 4 + 0][r] = pa[i].x;
                As[nxt][kq * 4 + 1][r] = pa[i].y;
                As[nxt][kq * 4 + 2][r] = pa[i].z;
                As[nxt][kq * 4 + 3][r] = pa[i].w;
                *(float4*)(&Bs[nxt][kr][nq * 4]) = pb[i];
            }
        }
        __syncthreads();
    }

    #pragma unroll
    for (int i = 0; i < 8; ++i) {
        #pragma unroll
        for (int j = 0; j < 8; j += 4) {
            float4 v;
            v.x = acc[i][j + 0];
            v.y = acc[i][j + 1];
            v.z = acc[i][j + 2];
            v.w = acc[i][j + 3];
            *(float4*)(C + (long long)(bm + row0 + i) * ldc + bn + col0 + j) = v;
        }
    }
}

// ---------------------------------------------------------------------------
// Row softmax, ncols = 2048, 256 threads, 8 elems/thread
// ---------------------------------------------------------------------------
__device__ __forceinline__ float warp_max(float v) {
    #pragma unroll
    for (int o = 16; o > 0; o >>= 1) v = fmaxf(v, __shfl_xor_sync(0xffffffffu, v, o));
    return v;
}
__device__ __forceinline__ float warp_sum(float v) {
    #pragma unroll
    for (int o = 16; o > 0; o >>= 1) v += __shfl_xor_sync(0xffffffffu, v, o);
    return v;
}

__global__ __launch_bounds__(256)
void softmax_kernel(float* __restrict__ S, int ncols)
{
    float* p = S + (long long)blockIdx.x * ncols;
    const int tid = threadIdx.x;
    const int wid = tid >> 5, lid = tid & 31;
    __shared__ float red[8];

    float v[8];
    float m = -1e30f;
    #pragma unroll
    for (int i = 0; i < 8; ++i) {
        v[i] = p[tid + i * 256];
        m = fmaxf(m, v[i]);
    }
    m = warp_max(m);
    if (lid == 0) red[wid] = m;
    __syncthreads();
    if (wid == 0) {
        float t = (lid < 8) ? red[lid] : -1e30f;   // FIX: each partial once
        t = warp_max(t);
        if (lid == 0) red[0] = t;
    }
    __syncthreads();
    m = red[0];
    __syncthreads();

    float s = 0.0f;
    #pragma unroll
    for (int i = 0; i < 8; ++i) {
        v[i] = expf(v[i] - m);
        s += v[i];
    }
    s = warp_sum(s);
    if (lid == 0) red[wid] = s;
    __syncthreads();
    if (wid == 0) {
        float t = (lid < 8) ? red[lid] : 0.0f;     // FIX: was red[lid&7] => 4x oversum
        t = warp_sum(t);
        if (lid == 0) red[0] = t;
    }
    __syncthreads();
    const float inv = 1.0f / red[0];

    #pragma unroll
    for (int i = 0; i < 8; ++i)
        p[tid + i * 256] = v[i] * inv;
}

// ---------------------------------------------------------------------------
extern "C" void kernel_launch(void* const* d_in, const int* in_sizes, int n_in,
                              void* d_out, int out_size)
{
    const float* q  = (const float*)d_in[0];
    const float* kv = (const float*)d_in[1];
    const float* Wq = (const float*)d_in[2];
    const float* Wk = (const float*)d_in[3];
    const float* Wv = (const float*)d_in[4];
    const float* Wo = (const float*)d_in[5];
    const float* bo = (const float*)d_in[6];
    float* out = (float*)d_out;

    float *qp, *kp, *vp, *ctx, *sc;
    cudaGetSymbolAddress((void**)&qp,  g_qp);
    cudaGetSymbolAddress((void**)&kp,  g_kp);
    cudaGetSymbolAddress((void**)&vp,  g_vp);
    cudaGetSymbolAddress((void**)&ctx, g_ctx);
    cudaGetSymbolAddress((void**)&sc,  g_scores);

    const dim3 blk(256);
    const int MT = BATCH * SEQ;              // 8192 flattened rows
    const float scale = 1.0f / 16.0f;        // HD^-0.5 = 256^-0.5

    // 1) qp = q @ Wq^T            [8192,1024] x [1024,1024]^T
    gemm_nt_kernel<<<dim3(DQ / BN, MT / BM, 1), blk>>>(
        q, Wq, nullptr, qp, DQ, DQ, DQ, DQ, 1,
        0, 0, 0, 0, 0, 0, 1.0f);

    // 2) kp = kv @ Wk^T           [8192,768] x [1024,768]^T
    gemm_nt_kernel<<<dim3(DQ / BN, MT / BM, 1), blk>>>(
        kv, Wk, nullptr, kp, DKV, DKV, DKV, DQ, 1,
        0, 0, 0, 0, 0, 0, 1.0f);

    // 3) vp = kv @ Wv^T
    gemm_nt_kernel<<<dim3(DQ / BN, MT / BM, 1), blk>>>(
        kv, Wv, nullptr, vp, DKV, DKV, DKV, DQ, 1,
        0, 0, 0, 0, 0, 0, 1.0f);

    // 4) scores[b,h] = scale * qh @ kh^T    per (b,h): [2048,256] x [2048,256]^T
    gemm_nt_kernel<<<dim3(SEQ / BN, SEQ / BM, BATCH * NH), blk>>>(
        qp, kp, nullptr, sc, HD, DQ, DQ, SEQ, NH,
        (long long)SEQ * DQ, HD,
        (long long)SEQ * DQ, HD,
        (long long)NH * SEQ * SEQ, (long long)SEQ * SEQ,
        scale);

    // 5) softmax over rows of scores
    softmax_kernel<<<dim3(BATCH * NH * SEQ), blk>>>(sc, SEQ);

    // 6) ctx[b,h] = P @ vh        per (b,h): [2048,2048] x [2048,256]
    gemm_nn_kernel<<<dim3(HD / BN, SEQ / BM, BATCH * NH), blk>>>(
        sc, vp, ctx, SEQ, SEQ, DQ, DQ, NH,
        (long long)NH * SEQ * SEQ, (long long)SEQ * SEQ,
        (long long)SEQ * DQ, HD,
        (long long)SEQ * DQ, HD);

    // 7) out = ctx @ Wo^T + bo    [8192,1024] x [1024,1024]^T
    gemm_nt_kernel<<<dim3(DQ / BN, MT / BM, 1), blk>>>(
        ctx, Wo, bo, out, DQ, DQ, DQ, DQ, 1,
        0, 0, 0, 0, 0, 0, 1.0f);
}

// round 5
// speedup vs baseline: 2.4531x; 2.4526x over previous
#include <cuda_runtime.h>
#include <cuda_fp16.h>
#include <cstdint>
#include <math.h>

// Problem constants
#define BATCH 4
#define SEQ   2048
#define DQ    1024
#define DKV   768
#define NH    4
#define HD    256

// HMMA GEMM tiling
#define TBM 128
#define TBN 128
#define TBK 32
#define NTHREADS 256
#define ROWB 80                   // smem row stride bytes: 32 halfs (64B) + 16B pad
#define TILEB (128 * ROWB)        // 10240 bytes per tile buffer

// -------- scratch (device globals; no cudaMalloc allowed) -------------------
__device__ float g_qp [(long long)BATCH * SEQ * DQ];          // 32 MB
__device__ float g_kp [(long long)BATCH * SEQ * DQ];          // 32 MB
__device__ float g_vpT[(long long)BATCH * DQ * SEQ];          // 32 MB (V transposed)
__device__ float g_ctx[(long long)BATCH * SEQ * DQ];          // 32 MB
__device__ float g_scores[(long long)BATCH * NH * SEQ * SEQ]; // 256 MB

// ---------------------------- helpers ---------------------------------------
__device__ __forceinline__ uint32_t smem_u32(const void* p) {
    uint32_t a;
    asm("{ .reg .u64 t; cvta.to.shared.u64 t, %1; cvt.u32.u64 %0, t; }"
        : "=r"(a) : "l"(p));
    return a;
}

__device__ __forceinline__ void ldsm4(uint32_t addr, uint32_t& r0, uint32_t& r1,
                                      uint32_t& r2, uint32_t& r3) {
    asm volatile("ldmatrix.sync.aligned.m8n8.x4.shared.b16 {%0,%1,%2,%3}, [%4];"
                 : "=r"(r0), "=r"(r1), "=r"(r2), "=r"(r3) : "r"(addr));
}

__device__ __forceinline__ void mma16816(float* c, const uint32_t* a,
                                         const uint32_t* b) {
    asm volatile(
        "mma.sync.aligned.m16n8k16.row.col.f32.f16.f16.f32 "
        "{%0,%1,%2,%3}, {%4,%5,%6,%7}, {%8,%9}, {%0,%1,%2,%3};"
        : "+f"(c[0]), "+f"(c[1]), "+f"(c[2]), "+f"(c[3])
        : "r"(a[0]), "r"(a[1]), "r"(a[2]), "r"(a[3]), "r"(b[0]), "r"(b[1]));
}

__device__ __forceinline__ uint32_t f2h2(float x, float y) {
    __half2 h = __floats2half2_rn(x, y);
    return *reinterpret_cast<uint32_t*>(&h);
}

// pack 8 consecutive fp32 (two float4) into 8 halfs (one uint4)
__device__ __forceinline__ uint4 pack8(const float4& f0, const float4& f1) {
    uint4 u;
    u.x = f2h2(f0.x, f0.y);
    u.y = f2h2(f0.z, f0.w);
    u.z = f2h2(f1.x, f1.y);
    u.w = f2h2(f1.z, f1.w);
    return u;
}

// ---------------------------------------------------------------------------
// HMMA fp16 NT GEMM:  C[m,n] = alpha * sum_k A[m,k]*B[n,k]  (+ bias[n])
// A: [M,K] K-contig (lda), B: [N,K] K-contig (ldb). fp32 in/out, fp16 compute,
// fp32 accumulate. Batched over blockIdx.z with (batch, head) strides.
// transC=1: C[(b*DQ + n)*SEQ + l], b = m>>11, l = m&2047 (V-transpose store).
// Requires M%128==0, N%128==0, K%32==0, lda/ldb multiple of 4.
// ---------------------------------------------------------------------------
__global__ __launch_bounds__(NTHREADS, 1)
void gemm_hmma(const float* __restrict__ A, const float* __restrict__ B,
               const float* __restrict__ bias, float* __restrict__ C,
               int K, int lda, int ldb, int ldc, int nh,
               long long sAb, long long sAh, long long sBb, long long sBh,
               long long sCb, long long sCh, float alpha, int transC)
{
    // smem: [A0][A1][B0][B1], each TILEB bytes
    __shared__ __align__(16) char sm[4 * TILEB];
    const uint32_t smbase = smem_u32(sm);

    const int tid = threadIdx.x;
    const int lane = tid & 31, wid = tid >> 5;
    const int wm = wid & 1, wn = wid >> 1;   // warp grid: 2 (m) x 4 (n)

    const int z = blockIdx.z, bz = z / nh, hz = z - bz * nh;
    A += bz * sAb + hz * sAh;
    B += bz * sBb + hz * sBh;
    C += bz * sCb + hz * sCh;
    const int bm = blockIdx.y * TBM, bn = blockIdx.x * TBN;

    // ---- staging addressing: 2 threads per row, 16 floats each -------------
    const int srow = tid >> 1, shalf = tid & 1;
    const float* Ap = A + (long long)(bm + srow) * lda + shalf * 16;
    const float* Bp = B + (long long)(bn + srow) * ldb + shalf * 16;
    const uint32_t sts_off = (uint32_t)srow * ROWB + shalf * 32;
    char* stsA = sm + sts_off;
    char* stsB = sm + 2 * TILEB + sts_off;

    // ---- ldmatrix lane addresses (buffer 0 base; add buf*TILEB later) ------
    // A: tile t (m16): lanes 0-15 rows, lanes 16-31 rows with k-chunk +1
    uint32_t a_addr[4], b_addr[2];
    {
        const int ar = wm * 64 + (lane & 15);
        const int ac = (lane >> 4);                 // 0/1 -> k chunk within kstep
        #pragma unroll
        for (int t = 0; t < 4; ++t)
            a_addr[t] = smbase + (uint32_t)(ar + t * 16) * ROWB + ac * 16;
        // B: tile u (n16): groups of 8 lanes -> (n,chunk) = (+0,c0),(+0,c1),(+8,c0),(+8,c1)
        const int br = wn * 32 + (lane & 7) + ((lane >> 4) << 3);
        const int bc = (lane >> 3) & 1;
        #pragma unroll
        for (int u = 0; u < 2; ++u)
            b_addr[u] = smbase + 2 * TILEB + (uint32_t)(br + u * 16) * ROWB + bc * 16;
    }

    float c[4][4][4];
    #pragma unroll
    for (int t = 0; t < 4; ++t)
        #pragma unroll
        for (int j = 0; j < 4; ++j)
            #pragma unroll
            for (int r = 0; r < 4; ++r)
                c[t][j][r] = 0.0f;

    const int KT = K / TBK;

    float4 ra[4], rb[4];
    // prologue: tile 0 -> buffer 0
    #pragma unroll
    for (int i = 0; i < 4; ++i) {
        ra[i] = ((const float4*)Ap)[i];
        rb[i] = ((const float4*)Bp)[i];
    }
    *(uint4*)(stsA)      = pack8(ra[0], ra[1]);
    *(uint4*)(stsA + 16) = pack8(ra[2], ra[3]);
    *(uint4*)(stsB)      = pack8(rb[0], rb[1]);
    *(uint4*)(stsB + 16) = pack8(rb[2], rb[3]);
    __syncthreads();

    for (int kt = 0; kt < KT; ++kt) {
        const int cur = kt & 1;
        const bool more = (kt + 1) < KT;
        if (more) {
            const int kpos = (kt + 1) * TBK;
            #pragma unroll
            for (int i = 0; i < 4; ++i) {
                ra[i] = ((const float4*)(Ap + kpos))[i];
                rb[i] = ((const float4*)(Bp + kpos))[i];
            }
        }

        // compute on buffer cur
        const uint32_t boff = (uint32_t)cur * TILEB;
        #pragma unroll
        for (int s = 0; s < 2; ++s) {
            uint32_t af[4][4], bf[2][4];
            #pragma unroll
            for (int t = 0; t < 4; ++t)
                ldsm4(a_addr[t] + boff + s * 32, af[t][0], af[t][1], af[t][2], af[t][3]);
            #pragma unroll
            for (int u = 0; u < 2; ++u)
                ldsm4(b_addr[u] + boff + s * 32, bf[u][0], bf[u][1], bf[u][2], bf[u][3]);
            #pragma unroll
            for (int t = 0; t < 4; ++t)
                #pragma unroll
                for (int j = 0; j < 4; ++j)
                    mma16816(c[t][j], af[t], &bf[j >> 1][(j & 1) * 2]);
        }

        if (more) {
            char* dA = stsA + (cur ^ 1) * TILEB;
            char* dB = stsB + (cur ^ 1) * TILEB;
            *(uint4*)(dA)      = pack8(ra[0], ra[1]);
            *(uint4*)(dA + 16) = pack8(ra[2], ra[3]);
            *(uint4*)(dB)      = pack8(rb[0], rb[1]);
            *(uint4*)(dB + 16) = pack8(rb[2], rb[3]);
        }
        __syncthreads();
    }

    // ---- epilogue -----------------------------------------------------------
    #pragma unroll
    for (int t = 0; t < 4; ++t) {
        const int m0 = bm + wm * 64 + t * 16 + (lane >> 2);
        #pragma unroll
        for (int j = 0; j < 4; ++j) {
            const int n0 = bn + wn * 32 + j * 8 + (lane & 3) * 2;
            float v0 = c[t][j][0] * alpha;
            float v1 = c[t][j][1] * alpha;
            float v2 = c[t][j][2] * alpha;
            float v3 = c[t][j][3] * alpha;
            if (bias) {
                const float b0 = bias[n0], b1 = bias[n0 + 1];
                v0 += b0; v1 += b1; v2 += b0; v3 += b1;
            }
            if (!transC) {
                float2 lo = make_float2(v0, v1);
                float2 hi = make_float2(v2, v3);
                *(float2*)(C + (long long)m0 * ldc + n0) = lo;
                *(float2*)(C + (long long)(m0 + 8) * ldc + n0) = hi;
            } else {
                const int b0i = m0 >> 11, l0 = m0 & 2047;
                const int m1 = m0 + 8;
                const int b1i = m1 >> 11, l1 = m1 & 2047;
                C[(long long)(b0i * DQ + n0)     * SEQ + l0] = v0;
                C[(long long)(b0i * DQ + n0 + 1) * SEQ + l0] = v1;
                C[(long long)(b1i * DQ + n0)     * SEQ + l1] = v2;
                C[(long long)(b1i * DQ + n0 + 1) * SEQ + l1] = v3;
            }
        }
    }
}

// ---------------------------------------------------------------------------
// Row softmax, ncols = 2048, 256 threads, 8 elems/thread
// ---------------------------------------------------------------------------
__device__ __forceinline__ float warp_max(float v) {
    #pragma unroll
    for (int o = 16; o > 0; o >>= 1) v = fmaxf(v, __shfl_xor_sync(0xffffffffu, v, o));
    return v;
}
__device__ __forceinline__ float warp_sum(float v) {
    #pragma unroll
    for (int o = 16; o > 0; o >>= 1) v += __shfl_xor_sync(0xffffffffu, v, o);
    return v;
}

__global__ __launch_bounds__(256)
void softmax_kernel(float* __restrict__ S, int ncols)
{
    float* p = S + (long long)blockIdx.x * ncols;
    const int tid = threadIdx.x;
    const int wid = tid >> 5, lid = tid & 31;
    __shared__ float red[8];

    float v[8];
    float m = -1e30f;
    #pragma unroll
    for (int i = 0; i < 8; ++i) {
        v[i] = p[tid + i * 256];
        m = fmaxf(m, v[i]);
    }
    m = warp_max(m);
    if (lid == 0) red[wid] = m;
    __syncthreads();
    if (wid == 0) {
        float t = (lid < 8) ? red[lid] : -1e30f;
        t = warp_max(t);
        if (lid == 0) red[0] = t;
    }
    __syncthreads();
    m = red[0];
    __syncthreads();

    float s = 0.0f;
    #pragma unroll
    for (int i = 0; i < 8; ++i) {
        v[i] = expf(v[i] - m);
        s += v[i];
    }
    s = warp_sum(s);
    if (lid == 0) red[wid] = s;
    __syncthreads();
    if (wid == 0) {
        float t = (lid < 8) ? red[lid] : 0.0f;
        t = warp_sum(t);
        if (lid == 0) red[0] = t;
    }
    __syncthreads();
    const float inv = 1.0f / red[0];

    #pragma unroll
    for (int i = 0; i < 8; ++i)
        p[tid + i * 256] = v[i] * inv;
}

// ---------------------------------------------------------------------------
extern "C" void kernel_launch(void* const* d_in, const int* in_sizes, int n_in,
                              void* d_out, int out_size)
{
    const float* q  = (const float*)d_in[0];
    const float* kv = (const float*)d_in[1];
    const float* Wq = (const float*)d_in[2];
    const float* Wk = (const float*)d_in[3];
    const float* Wv = (const float*)d_in[4];
    const float* Wo = (const float*)d_in[5];
    const float* bo = (const float*)d_in[6];
    float* out = (float*)d_out;

    float *qp, *kp, *vpT, *ctx, *sc;
    cudaGetSymbolAddress((void**)&qp,  g_qp);
    cudaGetSymbolAddress((void**)&kp,  g_kp);
    cudaGetSymbolAddress((void**)&vpT, g_vpT);
    cudaGetSymbolAddress((void**)&ctx, g_ctx);
    cudaGetSymbolAddress((void**)&sc,  g_scores);

    const int MT = BATCH * SEQ;        // 8192
    const float scale = 1.0f / 16.0f;  // HD^-0.5

    // 1) qp = q @ Wq^T                  [8192,1024] = [8192,1024] x [1024,1024]^T
    gemm_hmma<<<dim3(DQ / TBN, MT / TBM, 1), NTHREADS>>>(
        q, Wq, nullptr, qp, DQ, DQ, DQ, DQ, 1,
        0, 0, 0, 0, 0, 0, 1.0f, 0);

    // 2) kp = kv @ Wk^T                 [8192,1024] = [8192,768] x [1024,768]^T
    gemm_hmma<<<dim3(DQ / TBN, MT / TBM, 1), NTHREADS>>>(
        kv, Wk, nullptr, kp, DKV, DKV, DKV, DQ, 1,
        0, 0, 0, 0, 0, 0, 1.0f, 0);

    // 3) vpT = (kv @ Wv^T)^T            stored [b, n(1024), l(2048)]
    gemm_hmma<<<dim3(DQ / TBN, MT / TBM, 1), NTHREADS>>>(
        kv, Wv, nullptr, vpT, DKV, DKV, DKV, 0, 1,
        0, 0, 0, 0, 0, 0, 1.0f, 1);

    // 4) scores[b,h] = scale * qh @ kh^T   per (b,h): [2048,2048], K=256
    gemm_hmma<<<dim3(SEQ / TBN, SEQ / TBM, BATCH * NH), NTHREADS>>>(
        qp, kp, nullptr, sc, HD, DQ, DQ, SEQ, NH,
        (long long)SEQ * DQ, HD,
        (long long)SEQ * DQ, HD,
        (long long)NH * SEQ * SEQ, (long long)SEQ * SEQ,
        scale, 0);

    // 5) softmax
    softmax_kernel<<<dim3(BATCH * NH * SEQ), dim3(256)>>>(sc, SEQ);

    // 6) ctx[b,h] = P @ vh == P @ vpT^T (NT)   per (b,h): [2048,256], K=2048
    gemm_hmma<<<dim3(HD / TBN, SEQ / TBM, BATCH * NH), NTHREADS>>>(
        sc, vpT, nullptr, ctx, SEQ, SEQ, SEQ, DQ, NH,
        (long long)NH * SEQ * SEQ, (long long)SEQ * SEQ,
        (long long)DQ * SEQ, (long long)HD * SEQ,
        (long long)SEQ * DQ, HD,
        1.0f, 0);

    // 7) out = ctx @ Wo^T + bo
    gemm_hmma<<<dim3(DQ / TBN, MT / TBM, 1), NTHREADS>>>(
        ctx, Wo, bo, out, DQ, DQ, DQ, DQ, 1,
        0, 0, 0, 0, 0, 0, 1.0f, 0);
}

// round 6
// speedup vs baseline: 4.8143x; 1.9625x over previous
#include <cuda_runtime.h>
#include <cuda_fp16.h>
#include <cstdint>
#include <math.h>

// Problem constants
#define BATCH 4
#define SEQ   2048
#define DQ    1024
#define DKV   768
#define NH    4
#define HD    256

// HMMA GEMM tiling
#define TBM 128
#define TBN 128
#define TBK 32
#define NTHREADS 256
#define ROWB  80                    // smem row stride: 32 halfs (64B) + 16B pad
#define ATILE (128 * ROWB)          // 10240 B per operand tile
#define STAGEB (2 * ATILE)          // 20480 B per pipeline stage (A+B)
#define NSTAGE 4
#define SMEM_TOTAL (NSTAGE * STAGEB)  // 81920 B

// -------- scratch (device globals; no cudaMalloc allowed) -------------------
__device__ __half g_q16 [(long long)BATCH * SEQ * DQ];
__device__ __half g_kv16[(long long)BATCH * SEQ * DKV];
__device__ __half g_wq16[DQ * DQ];
__device__ __half g_wk16[DQ * DKV];
__device__ __half g_wv16[DQ * DKV];
__device__ __half g_wo16[DQ * DQ];
__device__ __half g_qp16 [(long long)BATCH * SEQ * DQ];
__device__ __half g_kp16 [(long long)BATCH * SEQ * DQ];
__device__ __half g_vpT16[(long long)BATCH * DQ * SEQ];   // V transposed
__device__ __half g_ctx16[(long long)BATCH * SEQ * DQ];
__device__ float  g_scores[(long long)BATCH * NH * SEQ * SEQ]; // fp32, 256 MB
__device__ __half g_p16   [(long long)BATCH * NH * SEQ * SEQ]; // fp16 probs

// ---------------------------- helpers ---------------------------------------
__device__ __forceinline__ uint32_t smem_u32(const void* p) {
    uint32_t a;
    asm("{ .reg .u64 t; cvta.to.shared.u64 t, %1; cvt.u32.u64 %0, t; }"
        : "=r"(a) : "l"(p));
    return a;
}

__device__ __forceinline__ void cp16(uint32_t dst, const void* src) {
    asm volatile("cp.async.cg.shared.global [%0], [%1], 16;"
                 :: "r"(dst), "l"(src) : "memory");
}

__device__ __forceinline__ void ldsm4(uint32_t addr, uint32_t& r0, uint32_t& r1,
                                      uint32_t& r2, uint32_t& r3) {
    asm volatile("ldmatrix.sync.aligned.m8n8.x4.shared.b16 {%0,%1,%2,%3}, [%4];"
                 : "=r"(r0), "=r"(r1), "=r"(r2), "=r"(r3) : "r"(addr));
}

__device__ __forceinline__ void mma16816(float* c, const uint32_t* a,
                                         const uint32_t* b) {
    asm volatile(
        "mma.sync.aligned.m16n8k16.row.col.f32.f16.f16.f32 "
        "{%0,%1,%2,%3}, {%4,%5,%6,%7}, {%8,%9}, {%0,%1,%2,%3};"
        : "+f"(c[0]), "+f"(c[1]), "+f"(c[2]), "+f"(c[3])
        : "r"(a[0]), "r"(a[1]), "r"(a[2]), "r"(a[3]), "r"(b[0]), "r"(b[1]));
}

// ---------------------------------------------------------------------------
// fp32 -> fp16 conversion, vectorized (n must be multiple of 4)
// ---------------------------------------------------------------------------
__global__ void f2h_kernel(const float4* __restrict__ in, uint2* __restrict__ out,
                           long long n4)
{
    long long i = (long long)blockIdx.x * blockDim.x + threadIdx.x;
    if (i >= n4) return;
    float4 v = in[i];
    __half2 h0 = __floats2half2_rn(v.x, v.y);
    __half2 h1 = __floats2half2_rn(v.z, v.w);
    uint2 u;
    u.x = *reinterpret_cast<uint32_t*>(&h0);
    u.y = *reinterpret_cast<uint32_t*>(&h1);
    out[i] = u;
}

// ---------------------------------------------------------------------------
// HMMA fp16 NT GEMM with cp.async 4-stage pipeline.
//   C[m,n] = alpha * sum_k A[m,k]*B[n,k]  (+ bias[n] if mode 0)
// A: [M,K] fp16 K-contig (lda), B: [N,K] fp16 K-contig (ldb).
// outMode: 0 = fp32 C (+bias), 1 = fp16 C, 2 = fp16 C transposed
//          (C[(b*DQ + n)*SEQ + l], b=m>>11, l=m&2047).
// Requires M%128==0, N%128==0, K%32==0, KT=K/32 >= 4, lda/ldb mult of 8.
// ---------------------------------------------------------------------------
__global__ __launch_bounds__(NTHREADS, 1)
void gemm_hmma16(const __half* __restrict__ A, const __half* __restrict__ B,
                 const float* __restrict__ bias, void* __restrict__ Cv,
                 int K, int lda, int ldb, int ldc, int nh,
                 long long sAb, long long sAh, long long sBb, long long sBh,
                 long long sCb, long long sCh, float alpha, int outMode)
{
    extern __shared__ __align__(16) char sm[];
    const uint32_t smbase = smem_u32(sm);

    const int tid = threadIdx.x;
    const int lane = tid & 31, wid = tid >> 5;
    const int wm = wid & 1, wn = wid >> 1;   // warp grid: 2 (m) x 4 (n)

    const int z = blockIdx.z, bz = z / nh, hz = z - bz * nh;
    A += bz * sAb + hz * sAh;
    B += bz * sBb + hz * sBh;
    const int bm = blockIdx.y * TBM, bn = blockIdx.x * TBN;

    // ---- cp.async staging: thread -> 2 rows x 1 chunk per operand ----------
    const int srow = tid >> 2;            // 0..63
    const int sc   = tid & 3;             // 16B chunk in row
    const __half* gA = A + (long long)(bm + srow) * lda + sc * 8;
    const __half* gB = B + (long long)(bn + srow) * ldb + sc * 8;
    const uint32_t stsA = smbase + (uint32_t)srow * ROWB + sc * 16;
    const uint32_t stsB = stsA + ATILE;
    const long long a64 = 64LL * lda, b64 = 64LL * ldb;

    // ---- ldmatrix lane addresses (stage 0 base) ----------------------------
    uint32_t a_addr[4], b_addr[2];
    {
        const int ar = wm * 64 + (lane & 15);
        const int ac = lane >> 4;
        #pragma unroll
        for (int t = 0; t < 4; ++t)
            a_addr[t] = smbase + (uint32_t)(ar + t * 16) * ROWB + ac * 16;
        const int br = wn * 32 + (lane & 7) + ((lane >> 4) << 3);
        const int bc = (lane >> 3) & 1;
        #pragma unroll
        for (int u = 0; u < 2; ++u)
            b_addr[u] = smbase + ATILE + (uint32_t)(br + u * 16) * ROWB + bc * 16;
    }

    float c[4][4][4];
    #pragma unroll
    for (int t = 0; t < 4; ++t)
        #pragma unroll
        for (int j = 0; j < 4; ++j)
            #pragma unroll
            for (int r = 0; r < 4; ++r)
                c[t][j][r] = 0.0f;

    const int KT = K / TBK;

    // ---- prologue: stages 0..2 --------------------------------------------
    #pragma unroll
    for (int p = 0; p < NSTAGE - 1; ++p) {
        const uint32_t so = (uint32_t)p * STAGEB;
        const int kp = p * TBK;
        cp16(stsA + so, gA + kp);
        cp16(stsA + so + 64 * ROWB, gA + kp + a64);
        cp16(stsB + so, gB + kp);
        cp16(stsB + so + 64 * ROWB, gB + kp + b64);
        asm volatile("cp.async.commit_group;" ::: "memory");
    }

    for (int kt = 0; kt < KT; ++kt) {
        asm volatile("cp.async.wait_group %0;" :: "n"(NSTAGE - 2) : "memory");
        __syncthreads();

        // issue stage kt+3 (overwrites buffer consumed at kt-1)
        const int ns = kt + NSTAGE - 1;
        if (ns < KT) {
            const uint32_t so = (uint32_t)(ns & (NSTAGE - 1)) * STAGEB;
            const int kp = ns * TBK;
            cp16(stsA + so, gA + kp);
            cp16(stsA + so + 64 * ROWB, gA + kp + a64);
            cp16(stsB + so, gB + kp);
            cp16(stsB + so + 64 * ROWB, gB + kp + b64);
        }
        asm volatile("cp.async.commit_group;" ::: "memory");

        // ---- compute on stage kt&3: batch all LDSM, then all MMA ----------
        const uint32_t soff = (uint32_t)(kt & (NSTAGE - 1)) * STAGEB;
        uint32_t af[2][4][4], bf[2][2][4];
        #pragma unroll
        for (int s = 0; s < 2; ++s) {
            #pragma unroll
            for (int t = 0; t < 4; ++t)
                ldsm4(a_addr[t] + soff + s * 32,
                      af[s][t][0], af[s][t][1], af[s][t][2], af[s][t][3]);
            #pragma unroll
            for (int u = 0; u < 2; ++u)
                ldsm4(b_addr[u] + soff + s * 32,
                      bf[s][u][0], bf[s][u][1], bf[s][u][2], bf[s][u][3]);
        }
        #pragma unroll
        for (int s = 0; s < 2; ++s)
            #pragma unroll
            for (int t = 0; t < 4; ++t)
                #pragma unroll
                for (int j = 0; j < 4; ++j)
                    mma16816(c[t][j], af[s][t], &bf[s][j >> 1][(j & 1) * 2]);
    }

    // ---- epilogue -----------------------------------------------------------
    #pragma unroll
    for (int t = 0; t < 4; ++t) {
        const int m0 = bm + wm * 64 + t * 16 + (lane >> 2);
        #pragma unroll
        for (int j = 0; j < 4; ++j) {
            const int n0 = bn + wn * 32 + j * 8 + (lane & 3) * 2;
            float v0 = c[t][j][0] * alpha;
            float v1 = c[t][j][1] * alpha;
            float v2 = c[t][j][2] * alpha;
            float v3 = c[t][j][3] * alpha;
            if (outMode == 0) {
                float* C = (float*)Cv + bz * sCb + hz * sCh;
                if (bias) {
                    const float b0 = bias[n0], b1 = bias[n0 + 1];
                    v0 += b0; v1 += b1; v2 += b0; v3 += b1;
                }
                *(float2*)(C + (long long)m0 * ldc + n0) = make_float2(v0, v1);
                *(float2*)(C + (long long)(m0 + 8) * ldc + n0) = make_float2(v2, v3);
            } else if (outMode == 1) {
                __half* C = (__half*)Cv + bz * sCb + hz * sCh;
                __half2 lo = __floats2half2_rn(v0, v1);
                __half2 hi = __floats2half2_rn(v2, v3);
                *(__half2*)(C + (long long)m0 * ldc + n0) = lo;
                *(__half2*)(C + (long long)(m0 + 8) * ldc + n0) = hi;
            } else {
                __half* C = (__half*)Cv;
                const int b0i = m0 >> 11, l0 = m0 & 2047;
                const int m1 = m0 + 8;
                const int b1i = m1 >> 11, l1 = m1 & 2047;
                C[(long long)(b0i * DQ + n0)     * SEQ + l0] = __float2half_rn(v0);
                C[(long long)(b0i * DQ + n0 + 1) * SEQ + l0] = __float2half_rn(v1);
                C[(long long)(b1i * DQ + n0)     * SEQ + l1] = __float2half_rn(v2);
                C[(long long)(b1i * DQ + n0 + 1) * SEQ + l1] = __float2half_rn(v3);
            }
        }
    }
}

// ---------------------------------------------------------------------------
// Row softmax: read fp32 scores, write fp16 probs. ncols=2048, 256 threads,
// thread t owns cols [8t, 8t+8) -> contiguous 16B stores.
// ---------------------------------------------------------------------------
__device__ __forceinline__ float warp_max(float v) {
    #pragma unroll
    for (int o = 16; o > 0; o >>= 1) v = fmaxf(v, __shfl_xor_sync(0xffffffffu, v, o));
    return v;
}
__device__ __forceinline__ float warp_sum(float v) {
    #pragma unroll
    for (int o = 16; o > 0; o >>= 1) v += __shfl_xor_sync(0xffffffffu, v, o);
    return v;
}

__global__ __launch_bounds__(256)
void softmax_kernel(const float* __restrict__ S, __half* __restrict__ P)
{
    const long long rowoff = (long long)blockIdx.x * SEQ;
    const float* p = S + rowoff;
    const int tid = threadIdx.x;
    const int wid = tid >> 5, lid = tid & 31;
    __shared__ float red[8];

    float v[8];
    *(float4*)(&v[0]) = *(const float4*)(p + tid * 8);
    *(float4*)(&v[4]) = *(const float4*)(p + tid * 8 + 4);

    float m = -1e30f;
    #pragma unroll
    for (int i = 0; i < 8; ++i) m = fmaxf(m, v[i]);
    m = warp_max(m);
    if (lid == 0) red[wid] = m;
    __syncthreads();
    if (wid == 0) {
        float t = (lid < 8) ? red[lid] : -1e30f;
        t = warp_max(t);
        if (lid == 0) red[0] = t;
    }
    __syncthreads();
    m = red[0];
    __syncthreads();

    float s = 0.0f;
    #pragma unroll
    for (int i = 0; i < 8; ++i) {
        v[i] = expf(v[i] - m);
        s += v[i];
    }
    s = warp_sum(s);
    if (lid == 0) red[wid] = s;
    __syncthreads();
    if (wid == 0) {
        float t = (lid < 8) ? red[lid] : 0.0f;
        t = warp_sum(t);
        if (lid == 0) red[0] = t;
    }
    __syncthreads();
    const float inv = 1.0f / red[0];

    __half2 h[4];
    #pragma unroll
    for (int i = 0; i < 4; ++i)
        h[i] = __floats2half2_rn(v[2 * i] * inv, v[2 * i + 1] * inv);
    *(uint4*)(P + rowoff + tid * 8) = *(uint4*)h;
}

// ---------------------------------------------------------------------------
extern "C" void kernel_launch(void* const* d_in, const int* in_sizes, int n_in,
                              void* d_out, int out_size)
{
    const float* q  = (const float*)d_in[0];
    const float* kv = (const float*)d_in[1];
    const float* Wq = (const float*)d_in[2];
    const float* Wk = (const float*)d_in[3];
    const float* Wv = (const float*)d_in[4];
    const float* Wo = (const float*)d_in[5];
    const float* bo = (const float*)d_in[6];
    float* out = (float*)d_out;

    __half *q16, *kv16, *wq16, *wk16, *wv16, *wo16;
    __half *qp16, *kp16, *vpT16, *ctx16, *p16;
    float* sc;
    cudaGetSymbolAddress((void**)&q16,  g_q16);
    cudaGetSymbolAddress((void**)&kv16, g_kv16);
    cudaGetSymbolAddress((void**)&wq16, g_wq16);
    cudaGetSymbolAddress((void**)&wk16, g_wk16);
    cudaGetSymbolAddress((void**)&wv16, g_wv16);
    cudaGetSymbolAddress((void**)&wo16, g_wo16);
    cudaGetSymbolAddress((void**)&qp16,  g_qp16);
    cudaGetSymbolAddress((void**)&kp16,  g_kp16);
    cudaGetSymbolAddress((void**)&vpT16, g_vpT16);
    cudaGetSymbolAddress((void**)&ctx16, g_ctx16);
    cudaGetSymbolAddress((void**)&p16,   g_p16);
    cudaGetSymbolAddress((void**)&sc,    g_scores);

    cudaFuncSetAttribute(gemm_hmma16, cudaFuncAttributeMaxDynamicSharedMemorySize,
                         SMEM_TOTAL);

    const int MT = BATCH * SEQ;        // 8192
    const float scale = 1.0f / 16.0f;  // HD^-0.5

    // 0) fp32 -> fp16 conversions
    {
        struct { const float* src; __half* dst; long long n; } cv[6] = {
            { q,  q16,  (long long)BATCH * SEQ * DQ  },
            { kv, kv16, (long long)BATCH * SEQ * DKV },
            { Wq, wq16, (long long)DQ * DQ  },
            { Wk, wk16, (long long)DQ * DKV },
            { Wv, wv16, (long long)DQ * DKV },
            { Wo, wo16, (long long)DQ * DQ  },
        };
        for (int i = 0; i < 6; ++i) {
            long long n4 = cv[i].n / 4;
            int g = (int)((n4 + 255) / 256);
            f2h_kernel<<<g, 256>>>((const float4*)cv[i].src, (uint2*)cv[i].dst, n4);
        }
    }

    // 1) qp16 = q16 @ Wq16^T
    gemm_hmma16<<<dim3(DQ / TBN, MT / TBM, 1), NTHREADS, SMEM_TOTAL>>>(
        q16, wq16, nullptr, qp16, DQ, DQ, DQ, DQ, 1,
        0, 0, 0, 0, 0, 0, 1.0f, 1);

    // 2) kp16 = kv16 @ Wk16^T
    gemm_hmma16<<<dim3(DQ / TBN, MT / TBM, 1), NTHREADS, SMEM_TOTAL>>>(
        kv16, wk16, nullptr, kp16, DKV, DKV, DKV, DQ, 1,
        0, 0, 0, 0, 0, 0, 1.0f, 1);

    // 3) vpT16 = (kv16 @ Wv16^T)^T   stored [b, n(1024), l(2048)]
    gemm_hmma16<<<dim3(DQ / TBN, MT / TBM, 1), NTHREADS, SMEM_TOTAL>>>(
        kv16, wv16, nullptr, vpT16, DKV, DKV, DKV, 0, 1,
        0, 0, 0, 0, 0, 0, 1.0f, 2);

    // 4) scores[b,h] = scale * qh @ kh^T   (fp32 out)  per (b,h): [2048,2048], K=256
    gemm_hmma16<<<dim3(SEQ / TBN, SEQ / TBM, BATCH * NH), NTHREADS, SMEM_TOTAL>>>(
        qp16, kp16, nullptr, sc, HD, DQ, DQ, SEQ, NH,
        (long long)SEQ * DQ, HD,
        (long long)SEQ * DQ, HD,
        (long long)NH * SEQ * SEQ, (long long)SEQ * SEQ,
        scale, 0);

    // 5) softmax: fp32 scores -> fp16 probs
    softmax_kernel<<<dim3(BATCH * NH * SEQ), dim3(256)>>>(sc, p16);

    // 6) ctx16 = P @ vpT16^T (NT)   per (b,h): [2048,256], K=2048
    gemm_hmma16<<<dim3(HD / TBN, SEQ / TBM, BATCH * NH), NTHREADS, SMEM_TOTAL>>>(
        p16, vpT16, nullptr, ctx16, SEQ, SEQ, SEQ, DQ, NH,
        (long long)NH * SEQ * SEQ, (long long)SEQ * SEQ,
        (long long)DQ * SEQ, (long long)HD * SEQ,
        (long long)SEQ * DQ, HD,
        1.0f, 1);

    // 7) out = ctx16 @ Wo16^T + bo  (fp32 out)
    gemm_hmma16<<<dim3(DQ / TBN, MT / TBM, 1), NTHREADS, SMEM_TOTAL>>>(
        ctx16, wo16, bo, out, DQ, DQ, DQ, DQ, 1,
        0, 0, 0, 0, 0, 0, 1.0f, 0);
}

// round 7
// speedup vs baseline: 5.7468x; 1.1937x over previous
#include <cuda_runtime.h>
#include <cuda_fp16.h>
#include <cstdint>
#include <math.h>

// Problem constants
#define BATCH 4
#define SEQ   2048
#define DQ    1024
#define DKV   768
#define NH    4
#define HD    256

// HMMA GEMM tiling
#define TBM 128
#define TBN 128
#define TBK 32
#define NTHREADS 256
#define ROWB  80                    // smem row stride: 32 halfs (64B) + 16B pad
#define ATILE (128 * ROWB)          // 10240 B per operand tile
#define STAGEB (2 * ATILE)          // 20480 B per pipeline stage (A+B)
#define NSTAGE 4
#define SMEM_TOTAL (NSTAGE * STAGEB)  // 81920 B

// -------- scratch (device globals; no cudaMalloc allowed) -------------------
__device__ __half g_q16 [(long long)BATCH * SEQ * DQ];
__device__ __half g_kv16[(long long)BATCH * SEQ * DKV];
__device__ __half g_wq16[DQ * DQ];
__device__ __half g_wk16[DQ * DKV];
__device__ __half g_wv16[DQ * DKV];
__device__ __half g_wo16[DQ * DQ];
__device__ __half g_qp16 [(long long)BATCH * SEQ * DQ];
__device__ __half g_kp16 [(long long)BATCH * SEQ * DQ];
__device__ __half g_vpT16[(long long)BATCH * DQ * SEQ];   // V transposed
__device__ __half g_ctx16[(long long)BATCH * SEQ * DQ];
__device__ float  g_scores[(long long)BATCH * NH * SEQ * SEQ]; // fp32, 256 MB
__device__ __half g_p16   [(long long)BATCH * NH * SEQ * SEQ]; // fp16 probs

// ---------------------------- helpers ---------------------------------------
__device__ __forceinline__ uint32_t smem_u32(const void* p) {
    uint32_t a;
    asm("{ .reg .u64 t; cvta.to.shared.u64 t, %1; cvt.u32.u64 %0, t; }"
        : "=r"(a) : "l"(p));
    return a;
}

__device__ __forceinline__ void cp16(uint32_t dst, const void* src) {
    asm volatile("cp.async.cg.shared.global [%0], [%1], 16;"
                 :: "r"(dst), "l"(src) : "memory");
}

__device__ __forceinline__ void ldsm4(uint32_t addr, uint32_t& r0, uint32_t& r1,
                                      uint32_t& r2, uint32_t& r3) {
    asm volatile("ldmatrix.sync.aligned.m8n8.x4.shared.b16 {%0,%1,%2,%3}, [%4];"
                 : "=r"(r0), "=r"(r1), "=r"(r2), "=r"(r3) : "r"(addr));
}

__device__ __forceinline__ void mma16816(float* c, const uint32_t* a,
                                         const uint32_t* b) {
    asm volatile(
        "mma.sync.aligned.m16n8k16.row.col.f32.f16.f16.f32 "
        "{%0,%1,%2,%3}, {%4,%5,%6,%7}, {%8,%9}, {%0,%1,%2,%3};"
        : "+f"(c[0]), "+f"(c[1]), "+f"(c[2]), "+f"(c[3])
        : "r"(a[0]), "r"(a[1]), "r"(a[2]), "r"(a[3]), "r"(b[0]), "r"(b[1]));
}

// ---------------------------------------------------------------------------
// fp32 -> fp16 conversion, vectorized (n must be multiple of 4)
// ---------------------------------------------------------------------------
__global__ void f2h_kernel(const float4* __restrict__ in, uint2* __restrict__ out,
                           long long n4)
{
    long long i = (long long)blockIdx.x * blockDim.x + threadIdx.x;
    if (i >= n4) return;
    float4 v = in[i];
    __half2 h0 = __floats2half2_rn(v.x, v.y);
    __half2 h1 = __floats2half2_rn(v.z, v.w);
    uint2 u;
    u.x = *reinterpret_cast<uint32_t*>(&h0);
    u.y = *reinterpret_cast<uint32_t*>(&h1);
    out[i] = u;
}

// ---------------------------------------------------------------------------
// HMMA fp16 NT GEMM with cp.async 4-stage pipeline, 2 CTAs/SM.
//   C[m,n] = alpha * sum_k A[m,k]*B[n,k]  (+ bias[n] if mode 0)
// A: [M,K] fp16 K-contig (lda), B: [N,K] fp16 K-contig (ldb).
// Warp grid: 4 (m) x 2 (n); warp tile 32 x 64.
// outMode: 0 = fp32 C (+bias), 1 = fp16 C, 2 = fp16 C transposed
//          (C[(b*DQ + n)*SEQ + l], b=m>>11, l=m&2047).
// Requires M%128==0, N%128==0, K%32==0, KT=K/32 >= 4, lda/ldb mult of 8.
// ---------------------------------------------------------------------------
__global__ __launch_bounds__(NTHREADS, 2)
void gemm_hmma16(const __half* __restrict__ A, const __half* __restrict__ B,
                 const float* __restrict__ bias, void* __restrict__ Cv,
                 int K, int lda, int ldb, int ldc, int nh,
                 long long sAb, long long sAh, long long sBb, long long sBh,
                 long long sCb, long long sCh, float alpha, int outMode)
{
    extern __shared__ __align__(16) char sm[];
    const uint32_t smbase = smem_u32(sm);

    const int tid = threadIdx.x;
    const int lane = tid & 31, wid = tid >> 5;
    const int wm = wid & 3, wn = wid >> 2;   // warp grid: 4 (m) x 2 (n)

    const int z = blockIdx.z, bz = z / nh, hz = z - bz * nh;
    A += bz * sAb + hz * sAh;
    B += bz * sBb + hz * sBh;
    const int bm = blockIdx.y * TBM, bn = blockIdx.x * TBN;

    // ---- cp.async staging: thread -> 2 rows x 1 chunk per operand ----------
    const int srow = tid >> 2;            // 0..63
    const int sc   = tid & 3;             // 16B chunk in row
    const __half* gA = A + (long long)(bm + srow) * lda + sc * 8;
    const __half* gB = B + (long long)(bn + srow) * ldb + sc * 8;
    const uint32_t stsA = smbase + (uint32_t)srow * ROWB + sc * 16;
    const uint32_t stsB = stsA + ATILE;
    const long long a64 = 64LL * lda, b64 = 64LL * ldb;

    // ---- ldmatrix lane addresses (stage 0 base) ----------------------------
    // A: 2 m16 tiles at wm*32; lanes 0-15 rows, 16-31 k-chunk +1
    uint32_t a_addr[2], b_addr[4];
    {
        const int ar = wm * 32 + (lane & 15);
        const int ac = lane >> 4;
        #pragma unroll
        for (int t = 0; t < 2; ++t)
            a_addr[t] = smbase + (uint32_t)(ar + t * 16) * ROWB + ac * 16;
        // B: 4 n16 tiles at wn*64
        const int br = wn * 64 + (lane & 7) + ((lane >> 4) << 3);
        const int bc = (lane >> 3) & 1;
        #pragma unroll
        for (int u = 0; u < 4; ++u)
            b_addr[u] = smbase + ATILE + (uint32_t)(br + u * 16) * ROWB + bc * 16;
    }

    float c[2][8][4];
    #pragma unroll
    for (int t = 0; t < 2; ++t)
        #pragma unroll
        for (int j = 0; j < 8; ++j)
            #pragma unroll
            for (int r = 0; r < 4; ++r)
                c[t][j][r] = 0.0f;

    const int KT = K / TBK;

    // ---- prologue: stages 0..2 --------------------------------------------
    #pragma unroll
    for (int p = 0; p < NSTAGE - 1; ++p) {
        const uint32_t so = (uint32_t)p * STAGEB;
        const int kp = p * TBK;
        cp16(stsA + so, gA + kp);
        cp16(stsA + so + 64 * ROWB, gA + kp + a64);
        cp16(stsB + so, gB + kp);
        cp16(stsB + so + 64 * ROWB, gB + kp + b64);
        asm volatile("cp.async.commit_group;" ::: "memory");
    }

    for (int kt = 0; kt < KT; ++kt) {
        asm volatile("cp.async.wait_group %0;" :: "n"(NSTAGE - 2) : "memory");
        __syncthreads();

        // issue stage kt+3 (overwrites buffer consumed at kt-1)
        const int ns = kt + NSTAGE - 1;
        if (ns < KT) {
            const uint32_t so = (uint32_t)(ns & (NSTAGE - 1)) * STAGEB;
            const int kp = ns * TBK;
            cp16(stsA + so, gA + kp);
            cp16(stsA + so + 64 * ROWB, gA + kp + a64);
            cp16(stsB + so, gB + kp);
            cp16(stsB + so + 64 * ROWB, gB + kp + b64);
        }
        asm volatile("cp.async.commit_group;" ::: "memory");

        // ---- compute on stage kt&3: one k-step of frags at a time ---------
        const uint32_t soff = (uint32_t)(kt & (NSTAGE - 1)) * STAGEB;
        #pragma unroll
        for (int s = 0; s < 2; ++s) {
            uint32_t af[2][4], bf[4][4];
            #pragma unroll
            for (int t = 0; t < 2; ++t)
                ldsm4(a_addr[t] + soff + s * 32,
                      af[t][0], af[t][1], af[t][2], af[t][3]);
            #pragma unroll
            for (int u = 0; u < 4; ++u)
                ldsm4(b_addr[u] + soff + s * 32,
                      bf[u][0], bf[u][1], bf[u][2], bf[u][3]);
            #pragma unroll
            for (int t = 0; t < 2; ++t)
                #pragma unroll
                for (int j = 0; j < 8; ++j)
                    mma16816(c[t][j], af[t], &bf[j >> 1][(j & 1) * 2]);
        }
    }

    // ---- epilogue -----------------------------------------------------------
    #pragma unroll
    for (int t = 0; t < 2; ++t) {
        const int m0 = bm + wm * 32 + t * 16 + (lane >> 2);
        #pragma unroll
        for (int j = 0; j < 8; ++j) {
            const int n0 = bn + wn * 64 + j * 8 + (lane & 3) * 2;
            float v0 = c[t][j][0] * alpha;
            float v1 = c[t][j][1] * alpha;
            float v2 = c[t][j][2] * alpha;
            float v3 = c[t][j][3] * alpha;
            if (outMode == 0) {
                float* C = (float*)Cv + bz * sCb + hz * sCh;
                if (bias) {
                    const float b0 = bias[n0], b1 = bias[n0 + 1];
                    v0 += b0; v1 += b1; v2 += b0; v3 += b1;
                }
                *(float2*)(C + (long long)m0 * ldc + n0) = make_float2(v0, v1);
                *(float2*)(C + (long long)(m0 + 8) * ldc + n0) = make_float2(v2, v3);
            } else if (outMode == 1) {
                __half* C = (__half*)Cv + bz * sCb + hz * sCh;
                __half2 lo = __floats2half2_rn(v0, v1);
                __half2 hi = __floats2half2_rn(v2, v3);
                *(__half2*)(C + (long long)m0 * ldc + n0) = lo;
                *(__half2*)(C + (long long)(m0 + 8) * ldc + n0) = hi;
            } else {
                __half* C = (__half*)Cv;
                const int b0i = m0 >> 11, l0 = m0 & 2047;
                const int m1 = m0 + 8;
                const int b1i = m1 >> 11, l1 = m1 & 2047;
                C[(long long)(b0i * DQ + n0)     * SEQ + l0] = __float2half_rn(v0);
                C[(long long)(b0i * DQ + n0 + 1) * SEQ + l0] = __float2half_rn(v1);
                C[(long long)(b1i * DQ + n0)     * SEQ + l1] = __float2half_rn(v2);
                C[(long long)(b1i * DQ + n0 + 1) * SEQ + l1] = __float2half_rn(v3);
            }
        }
    }
}

// ---------------------------------------------------------------------------
// Row softmax: read fp32 scores, write fp16 probs. ncols=2048, 256 threads,
// thread t owns cols [8t, 8t+8) -> contiguous 16B loads/stores.
// ---------------------------------------------------------------------------
__device__ __forceinline__ float warp_max(float v) {
    #pragma unroll
    for (int o = 16; o > 0; o >>= 1) v = fmaxf(v, __shfl_xor_sync(0xffffffffu, v, o));
    return v;
}
__device__ __forceinline__ float warp_sum(float v) {
    #pragma unroll
    for (int o = 16; o > 0; o >>= 1) v += __shfl_xor_sync(0xffffffffu, v, o);
    return v;
}

__global__ __launch_bounds__(256)
void softmax_kernel(const float* __restrict__ S, __half* __restrict__ P)
{
    const long long rowoff = (long long)blockIdx.x * SEQ;
    const float* p = S + rowoff;
    const int tid = threadIdx.x;
    const int wid = tid >> 5, lid = tid & 31;
    __shared__ float red[8];

    float v[8];
    *(float4*)(&v[0]) = *(const float4*)(p + tid * 8);
    *(float4*)(&v[4]) = *(const float4*)(p + tid * 8 + 4);

    float m = -1e30f;
    #pragma unroll
    for (int i = 0; i < 8; ++i) m = fmaxf(m, v[i]);
    m = warp_max(m);
    if (lid == 0) red[wid] = m;
    __syncthreads();
    if (wid == 0) {
        float t = (lid < 8) ? red[lid] : -1e30f;
        t = warp_max(t);
        if (lid == 0) red[0] = t;
    }
    __syncthreads();
    m = red[0];
    __syncthreads();

    float s = 0.0f;
    #pragma unroll
    for (int i = 0; i < 8; ++i) {
        v[i] = expf(v[i] - m);
        s += v[i];
    }
    s = warp_sum(s);
    if (lid == 0) red[wid] = s;
    __syncthreads();
    if (wid == 0) {
        float t = (lid < 8) ? red[lid] : 0.0f;
        t = warp_sum(t);
        if (lid == 0) red[0] = t;
    }
    __syncthreads();
    const float inv = 1.0f / red[0];

    __half2 h[4];
    #pragma unroll
    for (int i = 0; i < 4; ++i)
        h[i] = __floats2half2_rn(v[2 * i] * inv, v[2 * i + 1] * inv);
    *(uint4*)(P + rowoff + tid * 8) = *(uint4*)h;
}

// ---------------------------------------------------------------------------
extern "C" void kernel_launch(void* const* d_in, const int* in_sizes, int n_in,
                              void* d_out, int out_size)
{
    const float* q  = (const float*)d_in[0];
    const float* kv = (const float*)d_in[1];
    const float* Wq = (const float*)d_in[2];
    const float* Wk = (const float*)d_in[3];
    const float* Wv = (const float*)d_in[4];
    const float* Wo = (const float*)d_in[5];
    const float* bo = (const float*)d_in[6];
    float* out = (float*)d_out;

    __half *q16, *kv16, *wq16, *wk16, *wv16, *wo16;
    __half *qp16, *kp16, *vpT16, *ctx16, *p16;
    float* sc;
    cudaGetSymbolAddress((void**)&q16,  g_q16);
    cudaGetSymbolAddress((void**)&kv16, g_kv16);
    cudaGetSymbolAddress((void**)&wq16, g_wq16);
    cudaGetSymbolAddress((void**)&wk16, g_wk16);
    cudaGetSymbolAddress((void**)&wv16, g_wv16);
    cudaGetSymbolAddress((void**)&wo16, g_wo16);
    cudaGetSymbolAddress((void**)&qp16,  g_qp16);
    cudaGetSymbolAddress((void**)&kp16,  g_kp16);
    cudaGetSymbolAddress((void**)&vpT16, g_vpT16);
    cudaGetSymbolAddress((void**)&ctx16, g_ctx16);
    cudaGetSymbolAddress((void**)&p16,   g_p16);
    cudaGetSymbolAddress((void**)&sc,    g_scores);

    cudaFuncSetAttribute(gemm_hmma16, cudaFuncAttributeMaxDynamicSharedMemorySize,
                         SMEM_TOTAL);

    const int MT = BATCH * SEQ;        // 8192
    const float scale = 1.0f / 16.0f;  // HD^-0.5

    // 0) fp32 -> fp16 conversions
    {
        struct { const float* src; __half* dst; long long n; } cv[6] = {
            { q,  q16,  (long long)BATCH * SEQ * DQ  },
            { kv, kv16, (long long)BATCH * SEQ * DKV },
            { Wq, wq16, (long long)DQ * DQ  },
            { Wk, wk16, (long long)DQ * DKV },
            { Wv, wv16, (long long)DQ * DKV },
            { Wo, wo16, (long long)DQ * DQ  },
        };
        for (int i = 0; i < 6; ++i) {
            long long n4 = cv[i].n / 4;
            int g = (int)((n4 + 255) / 256);
            f2h_kernel<<<g, 256>>>((const float4*)cv[i].src, (uint2*)cv[i].dst, n4);
        }
    }

    // 1) qp16 = q16 @ Wq16^T
    gemm_hmma16<<<dim3(DQ / TBN, MT / TBM, 1), NTHREADS, SMEM_TOTAL>>>(
        q16, wq16, nullptr, qp16, DQ, DQ, DQ, DQ, 1,
        0, 0, 0, 0, 0, 0, 1.0f, 1);

    // 2) kp16 = kv16 @ Wk16^T
    gemm_hmma16<<<dim3(DQ / TBN, MT / TBM, 1), NTHREADS, SMEM_TOTAL>>>(
        kv16, wk16, nullptr, kp16, DKV, DKV, DKV, DQ, 1,
        0, 0, 0, 0, 0, 0, 1.0f, 1);

    // 3) vpT16 = (kv16 @ Wv16^T)^T   stored [b, n(1024), l(2048)]
    gemm_hmma16<<<dim3(DQ / TBN, MT / TBM, 1), NTHREADS, SMEM_TOTAL>>>(
        kv16, wv16, nullptr, vpT16, DKV, DKV, DKV, 0, 1,
        0, 0, 0, 0, 0, 0, 1.0f, 2);

    // 4) scores[b,h] = scale * qh @ kh^T   (fp32 out)  per (b,h): [2048,2048], K=256
    gemm_hmma16<<<dim3(SEQ / TBN, SEQ / TBM, BATCH * NH), NTHREADS, SMEM_TOTAL>>>(
        qp16, kp16, nullptr, sc, HD, DQ, DQ, SEQ, NH,
        (long long)SEQ * DQ, HD,
        (long long)SEQ * DQ, HD,
        (long long)NH * SEQ * SEQ, (long long)SEQ * SEQ,
        scale, 0);

    // 5) softmax: fp32 scores -> fp16 probs
    softmax_kernel<<<dim3(BATCH * NH * SEQ), dim3(256)>>>(sc, p16);

    // 6) ctx16 = P @ vpT16^T (NT)   per (b,h): [2048,256], K=2048
    gemm_hmma16<<<dim3(HD / TBN, SEQ / TBM, BATCH * NH), NTHREADS, SMEM_TOTAL>>>(
        p16, vpT16, nullptr, ctx16, SEQ, SEQ, SEQ, DQ, NH,
        (long long)NH * SEQ * SEQ, (long long)SEQ * SEQ,
        (long long)DQ * SEQ, (long long)HD * SEQ,
        (long long)SEQ * DQ, HD,
        1.0f, 1);

    // 7) out = ctx16 @ Wo16^T + bo  (fp32 out)
    gemm_hmma16<<<dim3(DQ / TBN, MT / TBM, 1), NTHREADS, SMEM_TOTAL>>>(
        ctx16, wo16, bo, out, DQ, DQ, DQ, DQ, 1,
        0, 0, 0, 0, 0, 0, 1.0f, 0);
}